// round 5
// baseline (speedup 1.0000x reference)
#include <cuda_runtime.h>
#include <math.h>

// Problem dims (fixed by the reference)
#define S_LEN 2048
#define B_SZ  64
#define I_SZ  512
#define H_SZ  512
#define G_SZ  2048            // 4*H
#define M1    (S_LEN * B_SZ)  // 131072

#define NBLK 128

// ---------------- scratch (static device globals; no cudaMalloc allowed) ---
// g_xw layout: [S][4H][B]  (transposed so phase 2 reads batches contiguously)
__device__ float g_xw[(size_t)S_LEN * G_SZ * B_SZ];
// g_h layout: [2][H][B]  (k-major: batch contiguous)
__device__ float g_h[2][H_SZ * B_SZ];
__device__ int   g_flags[NBLK * 32];          // per-block step flags, 128B padded

// ---------------- packed f32x2 helpers (sm_100a native, see ptx_helpers) ---
__device__ __forceinline__ void ffma2(unsigned long long& d,
                                      unsigned long long a,
                                      unsigned long long b) {
    asm("fma.rn.f32x2 %0, %1, %2, %0;" : "+l"(d) : "l"(a), "l"(b));
}
__device__ __forceinline__ unsigned long long pack2(float x) {
    unsigned long long r;
    asm("mov.b64 %0, {%1, %1};" : "=l"(r) : "f"(x));
    return r;
}
__device__ __forceinline__ float2 unpack2(unsigned long long v) {
    float2 r;
    asm("mov.b64 {%0, %1}, %2;" : "=f"(r.x), "=f"(r.y) : "l"(v));
    return r;
}

// =====================================================================
// Phase 1: xW = x @ W + bias, output stored as [S][4H][B]
// 128x128 tile, BK=8, 8x8 micro-tile via f32x2 (8x4 packed accumulators)
// =====================================================================
#define BM 128
#define BN 128
#define BKK 8

__global__ __launch_bounds__(256) void gemm_xw_kernel(
    const float* __restrict__ A,     // x  [M1, I]   (m = s*64 + b)
    const float* __restrict__ Wm,    // W  [I, G]
    const float* __restrict__ bias,  // [G]
    float* __restrict__ C)           // g_xw [S][G][B]
{
    __shared__ float As[BKK][BM];
    __shared__ float Bs[BKK][BN];

    const int bx = blockIdx.x;   // N tile: 0..15
    const int by = blockIdx.y;   // M tile: 0..1023
    const int tid = threadIdx.x;

    const int arow = tid >> 1;          // 0..127
    const int acol = (tid & 1) << 2;    // 0,4
    const int brow = tid >> 5;          // 0..7
    const int bcol = (tid & 31) << 2;   // 0..124

    const float* Ag = A + (size_t)(by * BM + arow) * I_SZ + acol;
    const float* Bg = Wm + (size_t)brow * G_SZ + bx * BN + bcol;

    const int tr = (tid >> 4) << 3;
    const int tc = (tid & 15) << 3;

    unsigned long long acc[8][4];
#pragma unroll
    for (int i = 0; i < 8; i++)
#pragma unroll
        for (int j = 0; j < 4; j++) acc[i][j] = 0ULL;

    for (int k0 = 0; k0 < I_SZ; k0 += BKK) {
        float4 a4 = *(const float4*)(Ag + k0);
        As[acol + 0][arow] = a4.x;
        As[acol + 1][arow] = a4.y;
        As[acol + 2][arow] = a4.z;
        As[acol + 3][arow] = a4.w;
        *(float4*)&Bs[brow][bcol] = *(const float4*)(Bg + (size_t)k0 * G_SZ);
        __syncthreads();

#pragma unroll
        for (int k = 0; k < BKK; k++) {
            float4 al = *(const float4*)&As[k][tr];
            float4 ah = *(const float4*)&As[k][tr + 4];
            ulonglong2 bl_ = *(const ulonglong2*)&Bs[k][tc];
            ulonglong2 bh_ = *(const ulonglong2*)&Bs[k][tc + 4];
            unsigned long long ap[8];
            ap[0] = pack2(al.x); ap[1] = pack2(al.y);
            ap[2] = pack2(al.z); ap[3] = pack2(al.w);
            ap[4] = pack2(ah.x); ap[5] = pack2(ah.y);
            ap[6] = pack2(ah.z); ap[7] = pack2(ah.w);
#pragma unroll
            for (int i = 0; i < 8; i++) {
                ffma2(acc[i][0], ap[i], bl_.x);
                ffma2(acc[i][1], ap[i], bl_.y);
                ffma2(acc[i][2], ap[i], bh_.x);
                ffma2(acc[i][3], ap[i], bh_.y);
            }
        }
        __syncthreads();
    }

    // epilogue: C[s][n][b] = acc + bias[n]
#pragma unroll
    for (int i = 0; i < 8; i++) {
        int m = by * BM + tr + i;
        int s = m >> 6;
        int b = m & 63;
        float* cb = C + (size_t)s * (G_SZ * B_SZ) + b;
#pragma unroll
        for (int j = 0; j < 4; j++) {
            int n = bx * BN + tc + 2 * j;
            float2 v = unpack2(acc[i][j]);
            cb[(size_t)(n + 0) * B_SZ] = v.x + bias[n + 0];
            cb[(size_t)(n + 1) * B_SZ] = v.y + bias[n + 1];
        }
    }
}

// =====================================================================
// reset kernel: zero flags + initial hidden state (called each launch)
// =====================================================================
__global__ void reset_kernel() {
    int tid = threadIdx.x + blockIdx.x * blockDim.x;
    for (int i = tid; i < NBLK * 32; i += blockDim.x * gridDim.x)
        g_flags[i] = 0;
    for (int i = tid; i < H_SZ * B_SZ; i += blockDim.x * gridDim.x)
        g_h[0][i] = 0.f;
}

// =====================================================================
// Phase 2: persistent recurrence kernel (f32x2 datapath)
// 128 blocks x 128 threads (1 CTA/SM by smem => all co-resident).
// Block bk owns hidden cols [bk*4, bk*4+4) => 16 gate-cols; their U
// values sit duplicated in SMEM all 2048 steps.
// h kept k-major [k][b] so batch pairs are native f32x2 operands.
// Thread = (bgrp, c): 8 batches x 1 gate-col (4 packed accumulators).
// =====================================================================
#define T2   128
#define HCPB 4
#define USTRIDE 1028                   // floats per gate-col (2*512 dup + 4 pad)
#define US_OFF 0
#define HS_OFF (16 * USTRIDE)          // 16448
#define GS_OFF (HS_OFF + H_SZ * B_SZ)  // 16448 + 32768 = 49216
#define GSTRIDE 17
#define SMEM_FLOATS (GS_OFF + B_SZ * GSTRIDE)   // 50304 -> 201216 bytes

__global__ __launch_bounds__(T2, 1) void lstm_rec_kernel(
    const float* __restrict__ xw,    // g_xw [S][G][B]
    const float* __restrict__ U,     // [H, G] row-major
    float* __restrict__ out_seq,     // [S, B, H]
    float* __restrict__ out_h,       // [B, H] or null
    float* __restrict__ out_c)       // [B, H] or null
{
    extern __shared__ float sm[];
    const int tid = threadIdx.x;
    const int bk  = blockIdx.x;
    const int hc0 = bk * HCPB;

    // ---- build duplicated-U slice in SMEM: us[c][2k] = us[c][2k+1] = U[k][gcol(c)]
    for (int i = tid; i < 16 * H_SZ; i += T2) {
        int c = i >> 9, k = i & 511;
        int gcol = (c >> 2) * H_SZ + hc0 + (c & 3);
        float u = U[(size_t)k * G_SZ + gcol];
        *(float2*)&sm[US_OFF + c * USTRIDE + 2 * k] = make_float2(u, u);
    }
    __syncthreads();

    const int c    = tid & 15;            // gate-col 0..15
    const int gcol = (c >> 2) * H_SZ + hc0 + (c & 3);
    const int b0   = (tid >> 4) * 8;      // batch group base (8 groups)

    const ulonglong2* up2 = (const ulonglong2*)&sm[US_OFF + c * USTRIDE];
    const char* hb = (const char*)&sm[HS_OFF + b0];   // k stride = 256 bytes

    // elementwise mapping: thread -> (batch eb, hidden j pair)
    const int eb  = tid >> 1;
    const int ej0 = (tid & 1) * 2;
    float creg0 = 0.f, creg1 = 0.f;       // cell state lives in registers

    volatile int* flags = (volatile int*)g_flags;

    for (int t = 0; t < S_LEN; t++) {
        // ---- xw accumulator init (coalesced thanks to [S][G][B] layout) ----
        const ulonglong2* xp =
            (const ulonglong2*)(xw + ((size_t)t * G_SZ + gcol) * B_SZ + b0);
        ulonglong2 xa = __ldg(xp);        // batches b0..b0+3
        ulonglong2 xb = __ldg(xp + 1);    // batches b0+4..b0+7

        // ---- pull h(t) into SMEM (L2-only: other SMs wrote it) ----
        {
            const float4* hsrc = (const float4*)g_h[t & 1];
            float4* hdst = (float4*)&sm[HS_OFF];
            for (int i = tid; i < (H_SZ * B_SZ) / 4; i += T2)
                hdst[i] = __ldcg(hsrc + i);
        }
        __syncthreads();

        // ---- gates = xw + h @ U : 8 FFMA2 per 2 k's ----
        unsigned long long a0 = xa.x, a1 = xa.y, a2 = xb.x, a3 = xb.y;
#pragma unroll 4
        for (int kk = 0; kk < H_SZ / 2; kk++) {
            ulonglong2 u  = up2[kk];
            ulonglong2 h0 = *(const ulonglong2*)(hb + kk * 512);
            ulonglong2 h1 = *(const ulonglong2*)(hb + kk * 512 + 16);
            ulonglong2 h2 = *(const ulonglong2*)(hb + kk * 512 + 256);
            ulonglong2 h3 = *(const ulonglong2*)(hb + kk * 512 + 256 + 16);
            ffma2(a0, h0.x, u.x); ffma2(a1, h0.y, u.x);
            ffma2(a2, h1.x, u.x); ffma2(a3, h1.y, u.x);
            ffma2(a0, h2.x, u.y); ffma2(a1, h2.y, u.y);
            ffma2(a2, h3.x, u.y); ffma2(a3, h3.y, u.y);
        }

        // ---- scatter gate values to gs[b][c] (stride 17: conflict-free) ----
        {
            float2 v;
            v = unpack2(a0);
            sm[GS_OFF + (b0 + 0) * GSTRIDE + c] = v.x;
            sm[GS_OFF + (b0 + 1) * GSTRIDE + c] = v.y;
            v = unpack2(a1);
            sm[GS_OFF + (b0 + 2) * GSTRIDE + c] = v.x;
            sm[GS_OFF + (b0 + 3) * GSTRIDE + c] = v.y;
            v = unpack2(a2);
            sm[GS_OFF + (b0 + 4) * GSTRIDE + c] = v.x;
            sm[GS_OFF + (b0 + 5) * GSTRIDE + c] = v.y;
            v = unpack2(a3);
            sm[GS_OFF + (b0 + 6) * GSTRIDE + c] = v.x;
            sm[GS_OFF + (b0 + 7) * GSTRIDE + c] = v.y;
        }
        __syncthreads();

        // ---- elementwise: 2 hidden cols per thread, c-state in regs ----
        float* hnext = g_h[(t + 1) & 1];
        const float* gb = &sm[GS_OFF + eb * GSTRIDE];
#pragma unroll
        for (int q = 0; q < 2; q++) {
            int j = ej0 + q;
            float gi = gb[0  + j];
            float gf = gb[4  + j];
            float gg = gb[8  + j];
            float go = gb[12 + j];
            float it = 1.f / (1.f + __expf(-gi));
            float ft = 1.f / (1.f + __expf(-gf));
            float gt = tanhf(gg);
            float ot = 1.f / (1.f + __expf(-go));
            float cold = q ? creg1 : creg0;
            float cnew = ft * cold + it * gt;
            if (q) creg1 = cnew; else creg0 = cnew;
            float hnew = ot * tanhf(cnew);

            hnext[(hc0 + j) * B_SZ + eb] = hnew;
            out_seq[(size_t)t * (B_SZ * H_SZ) + eb * H_SZ + hc0 + j] = hnew;
            if (t == S_LEN - 1) {
                if (out_h) out_h[eb * H_SZ + hc0 + j] = hnew;
                if (out_c) out_c[eb * H_SZ + hc0 + j] = cnew;
            }
        }

        // ---- distributed grid barrier (skip after last step) ----
        if (t < S_LEN - 1) {
            __threadfence();          // publish h stores
            __syncthreads();
            if (tid == 0)
                flags[bk * 32] = t + 1;           // padded slot, plain store
            while (flags[tid * 32] < t + 1) {     // one slot per thread (T2==NBLK)
                __nanosleep(32);
            }
            __threadfence();          // acquire
            __syncthreads();
        }
    }
}

// =====================================================================
// launch
// =====================================================================
extern "C" void kernel_launch(void* const* d_in, const int* in_sizes, int n_in,
                              void* d_out, int out_size) {
    const float* x    = (const float*)d_in[0];   // [S,B,I]
    const float* W    = (const float*)d_in[1];   // [I,4H]
    const float* U    = (const float*)d_in[2];   // [H,4H]
    const float* bias = (const float*)d_in[3];   // [4H]
    float* out = (float*)d_out;

    float* xw_ptr; cudaGetSymbolAddress((void**)&xw_ptr, g_xw);

    const long long seq_elems = (long long)S_LEN * B_SZ * H_SZ;
    float* out_h = nullptr;
    float* out_c = nullptr;
    if ((long long)out_size >= seq_elems + (long long)B_SZ * H_SZ)
        out_h = out + seq_elems;
    if ((long long)out_size >= seq_elems + 2LL * B_SZ * H_SZ)
        out_c = out + seq_elems + (long long)B_SZ * H_SZ;

    // Phase 1: input projection (writes [S][G][B])
    dim3 g1(G_SZ / BN, M1 / BM);        // (16, 1024)
    gemm_xw_kernel<<<g1, 256>>>(x, W, bias, xw_ptr);

    // reset flags + h0
    reset_kernel<<<32, 256>>>();

    // Phase 2: persistent recurrence
    static const int smem_bytes = SMEM_FLOATS * (int)sizeof(float);
    cudaFuncSetAttribute((const void*)lstm_rec_kernel,
                         cudaFuncAttributeMaxDynamicSharedMemorySize, smem_bytes);
    lstm_rec_kernel<<<NBLK, T2, smem_bytes>>>(xw_ptr, U, out, out_h, out_c);
}